// round 5
// baseline (speedup 1.0000x reference)
#include <cuda_runtime.h>
#include <cuda_fp16.h>
#include <cstdint>

// ---------------------------------------------------------------------------
// Fused persistent LSTM classifier, v4.
// v3 (layer-split warp specialization, tanh.approx) +
//  - ldmatrix.m8n8.x4 for all activation B-fragment loads (24->6 / 16->4 LDS)
//  - 4-way accumulator split (ih/hh chains separate, merged by FADD)
//  - staged LDSM issue to bound register liveness at the 128-reg ceiling
// ---------------------------------------------------------------------------

namespace {

constexpr int T_ = 512, I_ = 128, H_ = 64, E_ = 128, C_ = 100;
constexpr int BT = 8, NCTA = 128, NTHR = 512;

constexpr int SWI = 136;   // W_ih0 row stride (halves)
constexpr int SWH = 72;    // K=64 weight row stride
constexpr int SXS = 136;   // x row stride  (272B -> LDSM banks 4r, clean)
constexpr int SHS = 72;    // h row stride  (144B -> LDSM banks 4r, clean)

constexpr int XBUF_B = BT * SXS * 2;   // 2176 bytes per x buffer
constexpr int HBUF_B = BT * SHS * 2;   // 1152 bytes per h buffer

constexpr int OFF_WIH0 = 0;        // 69632
constexpr int OFF_WHH0 = 69632;    // 36864
constexpr int OFF_WIH1 = 106496;
constexpr int OFF_WHH1 = 143360;
constexpr int OFF_B0   = 180224;
constexpr int OFF_B1   = 181248;
constexpr int OFF_X    = 182272;   // 2 * 2176
constexpr int OFF_H0   = 186624;   // 2 * 1152
constexpr int OFF_H1   = 188928;
constexpr int OFF_HF   = 191232;
constexpr int OFF_E    = 193280;
constexpr int OFF_F    = 197376;
constexpr int SMEM_TOTAL = 201472;

#define BARRIER() asm volatile("bar.sync 0;" ::: "memory")

__device__ __forceinline__ float tanh_ap(float x) {
    float y;
    asm("tanh.approx.f32 %0, %1;" : "=f"(y) : "f"(x));
    return y;
}
__device__ __forceinline__ float fsig(float x) {
    return fmaf(0.5f, tanh_ap(0.5f * x), 0.5f);
}

__device__ __forceinline__ void mma4(float c[4], const uint32_t a[4],
                                     uint32_t b0, uint32_t b1) {
    asm volatile(
        "mma.sync.aligned.m16n8k16.row.col.f32.f16.f16.f32 "
        "{%0,%1,%2,%3},{%4,%5,%6,%7},{%8,%9},{%0,%1,%2,%3};\n"
        : "+f"(c[0]), "+f"(c[1]), "+f"(c[2]), "+f"(c[3])
        : "r"(a[0]), "r"(a[1]), "r"(a[2]), "r"(a[3]), "r"(b0), "r"(b1));
}

// ldmatrix x4 (non-trans): r0=b0(kt), r1=b1(kt), r2=b0(kt+1), r3=b1(kt+1)
__device__ __forceinline__ void ldsm4(uint32_t r[4], uint32_t a) {
    asm volatile("ldmatrix.sync.aligned.m8n8.x4.shared.b16 {%0,%1,%2,%3}, [%4];"
                 : "=r"(r[0]), "=r"(r[1]), "=r"(r[2]), "=r"(r[3]) : "r"(a));
}

template <int KT, int S>
__device__ __forceinline__ void load_w(const half* __restrict__ sW, int wc, int g,
                                       int t, uint32_t f[KT][2][4]) {
#pragma unroll
    for (int kt = 0; kt < KT; kt++)
#pragma unroll
        for (int u = 0; u < 2; u++) {
            const half* p = sW + (wc * 32 + u * 16 + g) * S + kt * 16 + 2 * t;
            f[kt][u][0] = *(const uint32_t*)(p);
            f[kt][u][1] = *(const uint32_t*)(p + 8 * S);
            f[kt][u][2] = *(const uint32_t*)(p + 8);
            f[kt][u][3] = *(const uint32_t*)(p + 8 * S + 8);
        }
}

__device__ __forceinline__ void acc_set(float a[2][4], const float b[2][2]) {
#pragma unroll
    for (int u = 0; u < 2; u++) {
        a[u][0] = b[u][0]; a[u][1] = b[u][0];
        a[u][2] = b[u][1]; a[u][3] = b[u][1];
    }
}
__device__ __forceinline__ void acc_zero(float a[2][4]) {
#pragma unroll
    for (int u = 0; u < 2; u++)
#pragma unroll
        for (int e = 0; e < 4; e++) a[u][e] = 0.f;
}

__global__ void __launch_bounds__(NTHR, 1)
lstm_fused(const float* __restrict__ x,
           const float* __restrict__ Wih0, const float* __restrict__ Whh0,
           const float* __restrict__ bih0, const float* __restrict__ bhh0,
           const float* __restrict__ Wih1, const float* __restrict__ Whh1,
           const float* __restrict__ bih1, const float* __restrict__ bhh1,
           const float* __restrict__ Wproj, const float* __restrict__ bproj,
           const float* __restrict__ Wfc1, const float* __restrict__ bfc1,
           const float* __restrict__ Wfc2, const float* __restrict__ bfc2,
           float* __restrict__ out)
{
    extern __shared__ unsigned char smem[];
    half*  sWih0 = (half*)(smem + OFF_WIH0);
    half*  sWhh0 = (half*)(smem + OFF_WHH0);
    half*  sWih1 = (half*)(smem + OFF_WIH1);
    half*  sWhh1 = (half*)(smem + OFF_WHH1);
    float* sB0   = (float*)(smem + OFF_B0);
    float* sB1   = (float*)(smem + OFF_B1);
    half*  sX    = (half*)(smem + OFF_X);
    half*  sH0   = (half*)(smem + OFF_H0);
    half*  sH1   = (half*)(smem + OFF_H1);
    float* sHF   = (float*)(smem + OFF_HF);
    float* sE    = (float*)(smem + OFF_E);
    float* sF    = (float*)(smem + OFF_F);

    const int tid  = threadIdx.x;
    const int lane = tid & 31;
    const int w    = tid >> 5;
    const int wc   = w & 7;
    const int g    = lane >> 2;
    const int t    = lane & 3;
    const int b0r  = blockIdx.x * BT;

    // LDSM per-thread base addresses (lane l -> batch row l&7, k-off (l>>3)*8)
    const uint32_t lrow = lane & 7, ltil = lane >> 3;
    const uint32_t aX  = (uint32_t)__cvta_generic_to_shared(sX)  + lrow * 272 + ltil * 16;
    const uint32_t aH0 = (uint32_t)__cvta_generic_to_shared(sH0) + lrow * 144 + ltil * 16;
    const uint32_t aH1 = (uint32_t)__cvta_generic_to_shared(sH1) + lrow * 144 + ltil * 16;

    // ---- stage permuted fp16 weights + fused biases ----
    for (int i = tid; i < 256 * 128; i += NTHR) {
        int p = i >> 7, k = i & 127;
        int m = (((p >> 4) & 1) * 2 + ((p >> 3) & 1)) * 64 + (p >> 5) * 8 + (p & 7);
        sWih0[p * SWI + k] = __float2half(Wih0[m * 128 + k]);
    }
    for (int i = tid; i < 256 * 64; i += NTHR) {
        int p = i >> 6, k = i & 63;
        int m = (((p >> 4) & 1) * 2 + ((p >> 3) & 1)) * 64 + (p >> 5) * 8 + (p & 7);
        sWhh0[p * SWH + k] = __float2half(Whh0[m * 64 + k]);
        sWih1[p * SWH + k] = __float2half(Wih1[m * 64 + k]);
        sWhh1[p * SWH + k] = __float2half(Whh1[m * 64 + k]);
    }
    for (int i = tid; i < 256; i += NTHR) {
        sB0[i] = bih0[i] + bhh0[i];
        sB1[i] = bih1[i] + bhh1[i];
    }
    for (int i = tid; i < 2 * BT * SHS; i += NTHR)
        sH1[i] = __float2half(0.f);

    // ---- x prefetch owned by L1 warps: warp = batch row, lane = 4 floats ----
    const int xr = wc, xi = lane * 4;
    const float* xrow = x + ((size_t)(b0r + xr) * T_) * I_ + xi;
    float4 xpre = make_float4(0.f, 0.f, 0.f, 0.f);
    if (w >= 8) {
        float4 xv = *(const float4*)(xrow);            // x(0) -> buf1
        half* xw = sX + BT * SXS;
        *(half2*)(xw + xr * SXS + xi)     = __floats2half2_rn(xv.x, xv.y);
        *(half2*)(xw + xr * SXS + xi + 2) = __floats2half2_rn(xv.z, xv.w);
        xpre = *(const float4*)(xrow + I_);            // x(1)
    }
    __syncthreads();

    const int n0 = 2 * t;
    const int j  = wc * 8 + g;

    if (w < 8) {
        // ================= layer-0 warps =================
        uint32_t fih0[8][2][4], fhh0[4][2][4];
        load_w<8, SWI>(sWih0, wc, g, t, fih0);
        load_w<4, SWH>(sWhh0, wc, g, t, fhh0);
        float bb0[2][2];
#pragma unroll
        for (int u = 0; u < 2; u++)
#pragma unroll
            for (int v = 0; v < 2; v++)
                bb0[u][v] = sB0[(2 * u + v) * 64 + wc * 8 + g];

        float c00 = 0.f, c01 = 0.f;

        {   // prologue: t=0 cell (no recurrent term)
            float a[2][4];
            acc_set(a, bb0);
            uint32_t bA[4], bB[4];
            ldsm4(bA, aX + XBUF_B);
            ldsm4(bB, aX + XBUF_B + 64);
#pragma unroll
            for (int c = 0; c < 4; c++) {
                uint32_t* bp = (c & 1) ? bB : bA;
                mma4(a[0], fih0[2 * c][0], bp[0], bp[1]);
                mma4(a[1], fih0[2 * c][1], bp[0], bp[1]);
                mma4(a[0], fih0[2 * c + 1][0], bp[2], bp[3]);
                mma4(a[1], fih0[2 * c + 1][1], bp[2], bp[3]);
                if (c == 0) ldsm4(bA, aX + XBUF_B + 128);
                if (c == 1) ldsm4(bB, aX + XBUF_B + 192);
            }
            float i0 = fsig(a[0][0]), i1 = fsig(a[0][1]);
            float g0 = tanh_ap(a[1][0]), g1 = tanh_ap(a[1][1]);
            float o0 = fsig(a[1][2]), o1 = fsig(a[1][3]);
            c00 = i0 * g0; c01 = i1 * g1;
            sH0[n0 * SHS + j]       = __float2half(o0 * tanh_ap(c00));
            sH0[(n0 + 1) * SHS + j] = __float2half(o1 * tanh_ap(c01));
        }
        BARRIER();

#pragma unroll 2
        for (int k = 0; k < T_; k++) {
            const int p = k & 1;
            const uint32_t ah = aH0 + p * HBUF_B;
            const uint32_t ax = aX + p * XBUF_B;
            uint32_t bh[4], bh2[4], bx[4], bx2[4];
            ldsm4(bh,  ah);
            ldsm4(bh2, ah + 64);
            ldsm4(bx,  ax);

            float aih[2][4], ahh[2][4];
            acc_set(aih, bb0);
            acc_zero(ahh);

            mma4(ahh[0], fhh0[0][0], bh[0], bh[1]);
            mma4(ahh[1], fhh0[0][1], bh[0], bh[1]);
            mma4(ahh[0], fhh0[1][0], bh[2], bh[3]);
            mma4(ahh[1], fhh0[1][1], bh[2], bh[3]);
            ldsm4(bx2, ax + 64);
            mma4(ahh[0], fhh0[2][0], bh2[0], bh2[1]);
            mma4(ahh[1], fhh0[2][1], bh2[0], bh2[1]);
            mma4(ahh[0], fhh0[3][0], bh2[2], bh2[3]);
            mma4(ahh[1], fhh0[3][1], bh2[2], bh2[3]);

            ldsm4(bh, ax + 128);                    // reuse regs: x kt4,5
            mma4(aih[0], fih0[0][0], bx[0], bx[1]);
            mma4(aih[1], fih0[0][1], bx[0], bx[1]);
            mma4(aih[0], fih0[1][0], bx[2], bx[3]);
            mma4(aih[1], fih0[1][1], bx[2], bx[3]);
            ldsm4(bh2, ax + 192);                   // x kt6,7
            mma4(aih[0], fih0[2][0], bx2[0], bx2[1]);
            mma4(aih[1], fih0[2][1], bx2[0], bx2[1]);
            mma4(aih[0], fih0[3][0], bx2[2], bx2[3]);
            mma4(aih[1], fih0[3][1], bx2[2], bx2[3]);
            mma4(aih[0], fih0[4][0], bh[0], bh[1]);
            mma4(aih[1], fih0[4][1], bh[0], bh[1]);
            mma4(aih[0], fih0[5][0], bh[2], bh[3]);
            mma4(aih[1], fih0[5][1], bh[2], bh[3]);
            mma4(aih[0], fih0[6][0], bh2[0], bh2[1]);
            mma4(aih[1], fih0[6][1], bh2[0], bh2[1]);
            mma4(aih[0], fih0[7][0], bh2[2], bh2[3]);
            mma4(aih[1], fih0[7][1], bh2[2], bh2[3]);

            float a0[4], a1[4];
#pragma unroll
            for (int e = 0; e < 4; e++) {
                a0[e] = aih[0][e] + ahh[0][e];
                a1[e] = aih[1][e] + ahh[1][e];
            }
            float i0 = fsig(a0[0]), i1 = fsig(a0[1]);
            float f0 = fsig(a0[2]), f1 = fsig(a0[3]);
            float g0 = tanh_ap(a1[0]), g1 = tanh_ap(a1[1]);
            float o0 = fsig(a1[2]), o1 = fsig(a1[3]);
            c00 = f0 * c00 + i0 * g0;
            c01 = f1 * c01 + i1 * g1;
            half* h0w = sH0 + (1 - p) * (BT * SHS);
            h0w[n0 * SHS + j]       = __float2half(o0 * tanh_ap(c00));
            h0w[(n0 + 1) * SHS + j] = __float2half(o1 * tanh_ap(c01));
            BARRIER();
        }
    } else {
        // ================= layer-1 warps =================
        uint32_t fih1[4][2][4], fhh1[4][2][4];
        load_w<4, SWH>(sWih1, wc, g, t, fih1);
        load_w<4, SWH>(sWhh1, wc, g, t, fhh1);
        float bb1[2][2];
#pragma unroll
        for (int u = 0; u < 2; u++)
#pragma unroll
            for (int v = 0; v < 2; v++)
                bb1[u][v] = sB1[(2 * u + v) * 64 + wc * 8 + g];

        float c10 = 0.f, c11 = 0.f;

        {   // commit x(1) -> buf0, fetch x(2)
            half* xw = sX;
            *(half2*)(xw + xr * SXS + xi)     = __floats2half2_rn(xpre.x, xpre.y);
            *(half2*)(xw + xr * SXS + xi + 2) = __floats2half2_rn(xpre.z, xpre.w);
            xpre = *(const float4*)(xrow + 2 * (size_t)I_);
        }
        BARRIER();

#pragma unroll 2
        for (int k = 0; k < T_; k++) {
            const int p = k & 1;
            {   // x pipeline first: commit x(k+2) -> buf 1-p, launch LDG x(k+3)
                half* xw = sX + (1 - p) * (BT * SXS);
                *(half2*)(xw + xr * SXS + xi)     = __floats2half2_rn(xpre.x, xpre.y);
                *(half2*)(xw + xr * SXS + xi + 2) = __floats2half2_rn(xpre.z, xpre.w);
                int tn = k + 3; if (tn > T_ - 1) tn = T_ - 1;
                xpre = *(const float4*)(xrow + (size_t)tn * I_);
            }
            uint32_t b0f[4], b0g[4], b1f[4], b1g[4];
            ldsm4(b0f, aH0 + p * HBUF_B);
            ldsm4(b0g, aH0 + p * HBUF_B + 64);
            ldsm4(b1f, aH1 + p * HBUF_B);
            ldsm4(b1g, aH1 + p * HBUF_B + 64);

            float aA[2][4], aB[2][4];
            acc_set(aA, bb1);
            acc_zero(aB);

            mma4(aA[0], fih1[0][0], b0f[0], b0f[1]);
            mma4(aA[1], fih1[0][1], b0f[0], b0f[1]);
            mma4(aB[0], fhh1[0][0], b1f[0], b1f[1]);
            mma4(aB[1], fhh1[0][1], b1f[0], b1f[1]);
            mma4(aA[0], fih1[1][0], b0f[2], b0f[3]);
            mma4(aA[1], fih1[1][1], b0f[2], b0f[3]);
            mma4(aB[0], fhh1[1][0], b1f[2], b1f[3]);
            mma4(aB[1], fhh1[1][1], b1f[2], b1f[3]);
            mma4(aA[0], fih1[2][0], b0g[0], b0g[1]);
            mma4(aA[1], fih1[2][1], b0g[0], b0g[1]);
            mma4(aB[0], fhh1[2][0], b1g[0], b1g[1]);
            mma4(aB[1], fhh1[2][1], b1g[0], b1g[1]);
            mma4(aA[0], fih1[3][0], b0g[2], b0g[3]);
            mma4(aA[1], fih1[3][1], b0g[2], b0g[3]);
            mma4(aB[0], fhh1[3][0], b1g[2], b1g[3]);
            mma4(aB[1], fhh1[3][1], b1g[2], b1g[3]);

            float a0[4], a1[4];
#pragma unroll
            for (int e = 0; e < 4; e++) {
                a0[e] = aA[0][e] + aB[0][e];
                a1[e] = aA[1][e] + aB[1][e];
            }
            float i0 = fsig(a0[0]), i1 = fsig(a0[1]);
            float f0 = fsig(a0[2]), f1 = fsig(a0[3]);
            float g0 = tanh_ap(a1[0]), g1 = tanh_ap(a1[1]);
            float o0 = fsig(a1[2]), o1 = fsig(a1[3]);
            c10 = f0 * c10 + i0 * g0;
            c11 = f1 * c11 + i1 * g1;
            float h0v = o0 * tanh_ap(c10), h1v = o1 * tanh_ap(c11);
            half* h1w = sH1 + (1 - p) * (BT * SHS);
            h1w[n0 * SHS + j]       = __float2half(h0v);
            h1w[(n0 + 1) * SHS + j] = __float2half(h1v);
            if (k == T_ - 1) {
                sHF[n0 * H_ + j]       = h0v;
                sHF[(n0 + 1) * H_ + j] = h1v;
            }
            BARRIER();
        }
    }

    // ---- head ----
#pragma unroll
    for (int q = 0; q < 2; q++) {
        int idx = tid + q * NTHR;
        int r = idx >> 7, e = idx & 127;
        float a = bproj[e];
        const float* wp = Wproj + e * H_;
        const float* hp = sHF + r * H_;
#pragma unroll 8
        for (int kk = 0; kk < H_; kk++) a += hp[kk] * wp[kk];
        sE[r * E_ + e] = fmaxf(a, 0.f);
    }
    __syncthreads();
#pragma unroll
    for (int q = 0; q < 2; q++) {
        int idx = tid + q * NTHR;
        int r = idx >> 7, e = idx & 127;
        float a = bfc1[e];
        const float* wp = Wfc1 + e * E_;
        const float* hp = sE + r * E_;
#pragma unroll 8
        for (int kk = 0; kk < E_; kk++) a += hp[kk] * wp[kk];
        sF[r * E_ + e] = fmaxf(a, 0.f);
    }
    __syncthreads();
    for (int idx = tid; idx < BT * C_; idx += NTHR) {
        int r = idx / C_, c = idx - r * C_;
        float a = bfc2[c];
        const float* wp = Wfc2 + c * E_;
        const float* hp = sF + r * E_;
#pragma unroll 8
        for (int kk = 0; kk < E_; kk++) a += hp[kk] * wp[kk];
        out[(size_t)(b0r + r) * C_ + c] = a;
    }
}

}  // namespace

extern "C" void kernel_launch(void* const* d_in, const int* in_sizes, int n_in,
                              void* d_out, int out_size) {
    cudaFuncSetAttribute(lstm_fused, cudaFuncAttributeMaxDynamicSharedMemorySize,
                         SMEM_TOTAL);
    lstm_fused<<<NCTA, NTHR, SMEM_TOTAL>>>(
        (const float*)d_in[0],
        (const float*)d_in[1],  (const float*)d_in[2],
        (const float*)d_in[3],  (const float*)d_in[4],
        (const float*)d_in[5],  (const float*)d_in[6],
        (const float*)d_in[7],  (const float*)d_in[8],
        (const float*)d_in[9],  (const float*)d_in[10],
        (const float*)d_in[11], (const float*)d_in[12],
        (const float*)d_in[13], (const float*)d_in[14],
        (float*)d_out);
}